// round 1
// baseline (speedup 1.0000x reference)
#include <cuda_runtime.h>
#include <math.h>

// Problem constants
static constexpr int Bc = 4;
static constexpr int Sc = 2048;
static constexpr int Ec = 1024;
static constexpr int Hc = 16;
static constexpr int Dc = 64;
static constexpr int Fc = 4096;
static constexpr int Mc = Bc * Sc;      // 8192 rows

// ---------------------------------------------------------------------------
// Scratch (device globals; no dynamic allocation allowed)
// ---------------------------------------------------------------------------
__device__ float g_ln [Mc * Ec];
__device__ float g_q  [Mc * Ec];
__device__ float g_k  [Mc * Ec];
__device__ float g_v  [Mc * Ec];
__device__ float g_ctx[Mc * Ec];
__device__ float g_x2 [Mc * Ec];
__device__ float g_hid[(size_t)Mc * Fc];

// ---------------------------------------------------------------------------
// LayerNorm: one block per row of E=1024, 256 threads, 4 elements/thread
// ---------------------------------------------------------------------------
__global__ __launch_bounds__(256) void ln_kernel(
    const float* __restrict__ x, const float* __restrict__ g,
    const float* __restrict__ b, float* __restrict__ out)
{
    __shared__ float red[8];
    const int row = blockIdx.x;
    const int t = threadIdx.x;
    const float* xr = x + (size_t)row * Ec;

    float v[4];
    float s = 0.f;
#pragma unroll
    for (int i = 0; i < 4; i++) { v[i] = xr[t + i * 256]; s += v[i]; }
#pragma unroll
    for (int m = 16; m; m >>= 1) s += __shfl_xor_sync(0xffffffffu, s, m);
    if ((t & 31) == 0) red[t >> 5] = s;
    __syncthreads();
    s = 0.f;
#pragma unroll
    for (int w = 0; w < 8; w++) s += red[w];
    const float mean = s * (1.f / Ec);
    __syncthreads();

    float sq = 0.f;
#pragma unroll
    for (int i = 0; i < 4; i++) { float d = v[i] - mean; sq += d * d; }
#pragma unroll
    for (int m = 16; m; m >>= 1) sq += __shfl_xor_sync(0xffffffffu, sq, m);
    if ((t & 31) == 0) red[t >> 5] = sq;
    __syncthreads();
    sq = 0.f;
#pragma unroll
    for (int w = 0; w < 8; w++) sq += red[w];
    const float rstd = rsqrtf(sq * (1.f / Ec) + 1e-5f);

    float* orow = out + (size_t)row * Ec;
#pragma unroll
    for (int i = 0; i < 4; i++) {
        int c = t + i * 256;
        orow[c] = (v[i] - mean) * rstd * g[c] + b[c];
    }
}

// ---------------------------------------------------------------------------
// NT GEMM: C[m,n] = sum_k A[m,k] * W[n,k] + bias[n] (+GELU) (+residual)
// 128x128 tile, BK=8, 256 threads, 8x8 register blocking
// ---------------------------------------------------------------------------
__device__ __forceinline__ float gelu_exact(float x) {
    return 0.5f * x * (1.f + erff(x * 0.70710678118654752f));
}

template <bool GELU, bool RES>
__global__ __launch_bounds__(256) void gemm_nt(
    const float* __restrict__ A, const float* __restrict__ W,
    const float* __restrict__ bias, const float* __restrict__ res,
    float* __restrict__ C, int M, int N, int K)
{
    __shared__ float As[8][132];
    __shared__ float Bs[8][132];

    const int t  = threadIdx.x;
    const int m0 = blockIdx.y * 128;
    const int n0 = blockIdx.x * 128;
    const int ty = t >> 4, tx = t & 15;

    const int lrow = t >> 1;           // 0..127
    const int lk4  = (t & 1) * 4;      // 0 or 4
    const float* Ap = A + (size_t)(m0 + lrow) * K + lk4;
    const float* Wp = W + (size_t)(n0 + lrow) * K + lk4;

    float acc[8][8] = {};

    for (int kk = 0; kk < K; kk += 8) {
        float4 av = *(const float4*)(Ap + kk);
        float4 bv = *(const float4*)(Wp + kk);
        As[lk4 + 0][lrow] = av.x; As[lk4 + 1][lrow] = av.y;
        As[lk4 + 2][lrow] = av.z; As[lk4 + 3][lrow] = av.w;
        Bs[lk4 + 0][lrow] = bv.x; Bs[lk4 + 1][lrow] = bv.y;
        Bs[lk4 + 2][lrow] = bv.z; Bs[lk4 + 3][lrow] = bv.w;
        __syncthreads();
#pragma unroll
        for (int k = 0; k < 8; k++) {
            float a[8], b[8];
            *(float4*)(a)     = *(const float4*)&As[k][ty * 8];
            *(float4*)(a + 4) = *(const float4*)&As[k][ty * 8 + 4];
            *(float4*)(b)     = *(const float4*)&Bs[k][tx * 8];
            *(float4*)(b + 4) = *(const float4*)&Bs[k][tx * 8 + 4];
#pragma unroll
            for (int i = 0; i < 8; i++)
#pragma unroll
                for (int j = 0; j < 8; j++)
                    acc[i][j] += a[i] * b[j];
        }
        __syncthreads();
    }

#pragma unroll
    for (int i = 0; i < 8; i++) {
        const int m = m0 + ty * 8 + i;
#pragma unroll
        for (int j = 0; j < 8; j++) {
            const int n = n0 + tx * 8 + j;
            float vv = acc[i][j] + bias[n];
            if (GELU) vv = gelu_exact(vv);
            if (RES)  vv += res[(size_t)m * N + n];
            C[(size_t)m * N + n] = vv;
        }
    }
}

// ---------------------------------------------------------------------------
// Flash attention: 64x64 tiles, online softmax, causal.
// q,k,v,ctx layout: [B, S, H, D] flattened == [B*S, E] with E = H*D.
// Grid: (S/64, B*H). 256 threads as 16x16, 4x4 patch per thread.
// ---------------------------------------------------------------------------
static constexpr int FA_SMEM = 4 * 64 * 65 * (int)sizeof(float); // 66560 B

__global__ __launch_bounds__(256) void flash_attn(
    const float* __restrict__ q, const float* __restrict__ k,
    const float* __restrict__ v, float* __restrict__ ctx)
{
    extern __shared__ float sm[];
    float* Qs = sm;               // [64][65]
    float* Ks = Qs + 64 * 65;
    float* Vs = Ks + 64 * 65;
    float* Ps = Vs + 64 * 65;

    const int qt = blockIdx.x;                 // query tile
    const int bh = blockIdx.y;
    const int bb = bh >> 4, hh = bh & 15;
    const int t  = threadIdx.x;
    const int ty = t >> 4, tx = t & 15;
    const size_t base = (size_t)bb * Sc * Ec + (size_t)hh * Dc;
    const int q0 = qt * 64;

    // Load Q tile (64 x 64)
#pragma unroll
    for (int i = 0; i < 4; i++) {
        int idx = t + i * 256;                 // 0..1023 float4 index
        int row = idx >> 4, c4 = (idx & 15) * 4;
        float4 val = *(const float4*)(q + base + (size_t)(q0 + row) * Ec + c4);
        float* dst = &Qs[row * 65 + c4];
        dst[0] = val.x; dst[1] = val.y; dst[2] = val.z; dst[3] = val.w;
    }

    float m_i[4], l_i[4], o[4][4] = {};
#pragma unroll
    for (int i = 0; i < 4; i++) { m_i[i] = -INFINITY; l_i[i] = 0.f; }

    for (int kt = 0; kt <= qt; kt++) {
        const int k0 = kt * 64;
        // Load K, V tiles
#pragma unroll
        for (int i = 0; i < 4; i++) {
            int idx = t + i * 256;
            int row = idx >> 4, c4 = (idx & 15) * 4;
            size_t goff = base + (size_t)(k0 + row) * Ec + c4;
            float4 kv4 = *(const float4*)(k + goff);
            float4 vv4 = *(const float4*)(v + goff);
            float* dk = &Ks[row * 65 + c4];
            float* dv = &Vs[row * 65 + c4];
            dk[0] = kv4.x; dk[1] = kv4.y; dk[2] = kv4.z; dk[3] = kv4.w;
            dv[0] = vv4.x; dv[1] = vv4.y; dv[2] = vv4.z; dv[3] = vv4.w;
        }
        __syncthreads();

        // S = Q K^T (4x4 patch per thread)
        float s[4][4] = {};
#pragma unroll 8
        for (int d = 0; d < 64; d++) {
            float qv[4], kv[4];
#pragma unroll
            for (int i = 0; i < 4; i++) qv[i] = Qs[(ty * 4 + i) * 65 + d];
#pragma unroll
            for (int j = 0; j < 4; j++) kv[j] = Ks[(tx * 4 + j) * 65 + d];
#pragma unroll
            for (int i = 0; i < 4; i++)
#pragma unroll
                for (int j = 0; j < 4; j++)
                    s[i][j] += qv[i] * kv[j];
        }

        const bool diag = (kt == qt);
#pragma unroll
        for (int i = 0; i < 4; i++)
#pragma unroll
            for (int j = 0; j < 4; j++) {
                s[i][j] *= 0.125f;             // 1/sqrt(64)
                if (diag && (tx * 4 + j) > (ty * 4 + i)) s[i][j] = -INFINITY;
            }

        // online softmax row statistics (rows owned by all 16 tx-threads of ty)
#pragma unroll
        for (int i = 0; i < 4; i++) {
            float mx = fmaxf(fmaxf(s[i][0], s[i][1]), fmaxf(s[i][2], s[i][3]));
#pragma unroll
            for (int msk = 8; msk; msk >>= 1)
                mx = fmaxf(mx, __shfl_xor_sync(0xffffffffu, mx, msk));
            const float mn = fmaxf(m_i[i], mx);
            const float alpha = __expf(m_i[i] - mn);
            m_i[i] = mn;
            float rs = 0.f;
#pragma unroll
            for (int j = 0; j < 4; j++) {
                s[i][j] = __expf(s[i][j] - mn);
                rs += s[i][j];
            }
#pragma unroll
            for (int msk = 8; msk; msk >>= 1)
                rs += __shfl_xor_sync(0xffffffffu, rs, msk);
            l_i[i] = l_i[i] * alpha + rs;
#pragma unroll
            for (int j = 0; j < 4; j++) {
                o[i][j] *= alpha;
                Ps[(ty * 4 + i) * 65 + tx * 4 + j] = s[i][j];
            }
        }
        __syncthreads();

        // O += P V
#pragma unroll 8
        for (int c = 0; c < 64; c++) {
            float pv[4], vv[4];
#pragma unroll
            for (int i = 0; i < 4; i++) pv[i] = Ps[(ty * 4 + i) * 65 + c];
#pragma unroll
            for (int j = 0; j < 4; j++) vv[j] = Vs[c * 65 + tx * 4 + j];
#pragma unroll
            for (int i = 0; i < 4; i++)
#pragma unroll
                for (int j = 0; j < 4; j++)
                    o[i][j] += pv[i] * vv[j];
        }
        __syncthreads();
    }

#pragma unroll
    for (int i = 0; i < 4; i++) {
        const float inv = 1.f / l_i[i];
#pragma unroll
        for (int j = 0; j < 4; j++)
            ctx[base + (size_t)(q0 + ty * 4 + i) * Ec + tx * 4 + j] = o[i][j] * inv;
    }
}

// ---------------------------------------------------------------------------
// Launch
// ---------------------------------------------------------------------------
extern "C" void kernel_launch(void* const* d_in, const int* in_sizes, int n_in,
                              void* d_out, int out_size)
{
    (void)in_sizes; (void)n_in; (void)out_size;
    const float* x     = (const float*)d_in[0];
    // d_in[1] = causal mask (tril), structure known — unused
    const float* ln1_g = (const float*)d_in[2];
    const float* ln1_b = (const float*)d_in[3];
    const float* Wq = (const float*)d_in[4];
    const float* bq = (const float*)d_in[5];
    const float* Wk = (const float*)d_in[6];
    const float* bk = (const float*)d_in[7];
    const float* Wv = (const float*)d_in[8];
    const float* bv = (const float*)d_in[9];
    const float* Wo = (const float*)d_in[10];
    const float* bo = (const float*)d_in[11];
    const float* ln2_g = (const float*)d_in[12];
    const float* ln2_b = (const float*)d_in[13];
    const float* W1 = (const float*)d_in[14];
    const float* b1 = (const float*)d_in[15];
    const float* W2 = (const float*)d_in[16];
    const float* b2 = (const float*)d_in[17];
    float* out = (float*)d_out;

    float *ln, *q, *k, *v, *ctx, *x2, *hid;
    cudaGetSymbolAddress((void**)&ln,  g_ln);
    cudaGetSymbolAddress((void**)&q,   g_q);
    cudaGetSymbolAddress((void**)&k,   g_k);
    cudaGetSymbolAddress((void**)&v,   g_v);
    cudaGetSymbolAddress((void**)&ctx, g_ctx);
    cudaGetSymbolAddress((void**)&x2,  g_x2);
    cudaGetSymbolAddress((void**)&hid, g_hid);

    cudaFuncSetAttribute(flash_attn, cudaFuncAttributeMaxDynamicSharedMemorySize, FA_SMEM);

    // x -> LN1
    ln_kernel<<<Mc, 256>>>(x, ln1_g, ln1_b, ln);
    // QKV projections
    gemm_nt<false, false><<<dim3(Ec / 128, Mc / 128), 256>>>(ln, Wq, bq, nullptr, q,  Mc, Ec, Ec);
    gemm_nt<false, false><<<dim3(Ec / 128, Mc / 128), 256>>>(ln, Wk, bk, nullptr, k,  Mc, Ec, Ec);
    gemm_nt<false, false><<<dim3(Ec / 128, Mc / 128), 256>>>(ln, Wv, bv, nullptr, v,  Mc, Ec, Ec);
    // attention
    flash_attn<<<dim3(Sc / 64, Bc * Hc), 256, FA_SMEM>>>(q, k, v, ctx);
    // O projection + residual(x) -> x2
    gemm_nt<false, true><<<dim3(Ec / 128, Mc / 128), 256>>>(ctx, Wo, bo, x, x2, Mc, Ec, Ec);
    // LN2
    ln_kernel<<<Mc, 256>>>(x2, ln2_g, ln2_b, ln);
    // FFN up + GELU
    gemm_nt<true, false><<<dim3(Fc / 128, Mc / 128), 256>>>(ln, W1, b1, nullptr, hid, Mc, Fc, Ec);
    // FFN down + residual(x2) -> out
    gemm_nt<false, true><<<dim3(Ec / 128, Mc / 128), 256>>>(hid, W2, b2, x2, out, Mc, Ec, Fc);
}

// round 3
// speedup vs baseline: 3.2883x; 3.2883x over previous
#include <cuda_runtime.h>
#include <cuda_bf16.h>
#include <math.h>
#include <cstdint>

static constexpr int Bc = 4;
static constexpr int Sc = 2048;
static constexpr int Ec = 1024;
static constexpr int Hc = 16;
static constexpr int Dc = 64;
static constexpr int Fc = 4096;
static constexpr int Mc = Bc * Sc;      // 8192 rows

// ---------------------------------------------------------------------------
// Scratch (device globals)
// ---------------------------------------------------------------------------
__device__ __nv_bfloat16 g_lnh[Mc * Ec], g_lnl[Mc * Ec];
__device__ __nv_bfloat16 g_qh [Mc * Ec], g_ql [Mc * Ec];
__device__ __nv_bfloat16 g_kh [Mc * Ec], g_kl [Mc * Ec];
__device__ __nv_bfloat16 g_vh [Mc * Ec], g_vl [Mc * Ec];
__device__ __nv_bfloat16 g_ch [Mc * Ec], g_cl [Mc * Ec];
__device__ float         g_x2 [Mc * Ec];
__device__ __nv_bfloat16 g_hh [(size_t)Mc * Fc], g_hl [(size_t)Mc * Fc];
__device__ __nv_bfloat16 g_wh [(size_t)Fc * Ec], g_wl [(size_t)Fc * Ec];

// ---------------------------------------------------------------------------
// PTX helpers (all plain sm_80+ features, safe at target sm_103)
// ---------------------------------------------------------------------------
__device__ __forceinline__ uint32_t smem_u32(const void* p) {
    uint32_t a;
    asm("{ .reg .u64 t; cvta.to.shared.u64 t, %1; cvt.u32.u64 %0, t; }" : "=r"(a) : "l"(p));
    return a;
}

#define CP16(dst, src) \
    asm volatile("cp.async.cg.shared.global [%0], [%1], 16;" :: "r"(dst), "l"(src))
#define CP_COMMIT() asm volatile("cp.async.commit_group;" ::: "memory")
#define CP_WAIT(n)  asm volatile("cp.async.wait_group %0;" :: "n"(n) : "memory")

__device__ __forceinline__ void ldsm_x4(uint32_t r[4], uint32_t addr) {
    asm volatile("ldmatrix.sync.aligned.m8n8.x4.shared.b16 {%0,%1,%2,%3}, [%4];"
        : "=r"(r[0]), "=r"(r[1]), "=r"(r[2]), "=r"(r[3]) : "r"(addr));
}
__device__ __forceinline__ void ldsm_x4_t(uint32_t r[4], uint32_t addr) {
    asm volatile("ldmatrix.sync.aligned.m8n8.x4.trans.shared.b16 {%0,%1,%2,%3}, [%4];"
        : "=r"(r[0]), "=r"(r[1]), "=r"(r[2]), "=r"(r[3]) : "r"(addr));
}
__device__ __forceinline__ void mma16816(float* c, const uint32_t* a,
                                         uint32_t b0, uint32_t b1) {
    asm volatile(
        "mma.sync.aligned.m16n8k16.row.col.f32.bf16.bf16.f32 "
        "{%0,%1,%2,%3}, {%4,%5,%6,%7}, {%8,%9}, {%0,%1,%2,%3};"
        : "+f"(c[0]), "+f"(c[1]), "+f"(c[2]), "+f"(c[3])
        : "r"(a[0]), "r"(a[1]), "r"(a[2]), "r"(a[3]), "r"(b0), "r"(b1));
}
// pack {even, odd} floats -> bf16x2 (low half = even)
__device__ __forceinline__ uint32_t pack_bf162(float even, float odd) {
    uint32_t r;
    asm("cvt.rn.bf16x2.f32 %0, %1, %2;" : "=r"(r) : "f"(odd), "f"(even));
    return r;
}

#define SWZ(row, c) (((uint32_t)(row)) * 128u + ((((uint32_t)(c)) ^ ((uint32_t)(row) & 7u)) << 4))

__device__ __forceinline__ float gelu_exact(float x) {
    return 0.5f * x * (1.f + erff(x * 0.70710678118654752f));
}

// ---------------------------------------------------------------------------
// LayerNorm -> split bf16 (hi, lo)
// ---------------------------------------------------------------------------
__global__ __launch_bounds__(256) void ln_split_kernel(
    const float* __restrict__ x, const float* __restrict__ g,
    const float* __restrict__ b, __nv_bfloat16* __restrict__ ohi,
    __nv_bfloat16* __restrict__ olo)
{
    __shared__ float red[8];
    const int row = blockIdx.x;
    const int t = threadIdx.x;
    const float* xr = x + (size_t)row * Ec;

    float v[4];
    float s = 0.f;
#pragma unroll
    for (int i = 0; i < 4; i++) { v[i] = xr[t + i * 256]; s += v[i]; }
#pragma unroll
    for (int m = 16; m; m >>= 1) s += __shfl_xor_sync(0xffffffffu, s, m);
    if ((t & 31) == 0) red[t >> 5] = s;
    __syncthreads();
    s = 0.f;
#pragma unroll
    for (int w = 0; w < 8; w++) s += red[w];
    const float mean = s * (1.f / Ec);
    __syncthreads();

    float sq = 0.f;
#pragma unroll
    for (int i = 0; i < 4; i++) { float d = v[i] - mean; sq += d * d; }
#pragma unroll
    for (int m = 16; m; m >>= 1) sq += __shfl_xor_sync(0xffffffffu, sq, m);
    if ((t & 31) == 0) red[t >> 5] = sq;
    __syncthreads();
    sq = 0.f;
#pragma unroll
    for (int w = 0; w < 8; w++) sq += red[w];
    const float rstd = rsqrtf(sq * (1.f / Ec) + 1e-5f);

#pragma unroll
    for (int i = 0; i < 4; i++) {
        int c = t + i * 256;
        float y = (v[i] - mean) * rstd * g[c] + b[c];
        __nv_bfloat16 h = __float2bfloat16(y);
        ohi[(size_t)row * Ec + c] = h;
        olo[(size_t)row * Ec + c] = __float2bfloat16(y - __bfloat162float(h));
    }
}

// ---------------------------------------------------------------------------
// fp32 -> (hi, lo) bf16 split (weights)
// ---------------------------------------------------------------------------
__global__ __launch_bounds__(256) void split_kernel(
    const float* __restrict__ x, __nv_bfloat16* __restrict__ hi,
    __nv_bfloat16* __restrict__ lo, int n4)
{
    int i = blockIdx.x * 256 + threadIdx.x;
    if (i >= n4) return;
    float4 v = ((const float4*)x)[i];
    float vv[4] = {v.x, v.y, v.z, v.w};
    __nv_bfloat16 h[4], l[4];
#pragma unroll
    for (int j = 0; j < 4; j++) {
        h[j] = __float2bfloat16(vv[j]);
        l[j] = __float2bfloat16(vv[j] - __bfloat162float(h[j]));
    }
    __nv_bfloat162* hp = (__nv_bfloat162*)(hi + 4 * (size_t)i);
    __nv_bfloat162* lp = (__nv_bfloat162*)(lo + 4 * (size_t)i);
    hp[0] = __halves2bfloat162(h[0], h[1]);
    hp[1] = __halves2bfloat162(h[2], h[3]);
    lp[0] = __halves2bfloat162(l[0], l[1]);
    lp[1] = __halves2bfloat162(l[2], l[3]);
}

// ---------------------------------------------------------------------------
// HMMA GEMM (NT): C = (Ahi+Alo)[M,K] @ (Bhi+Blo)[N,K]^T via 3-term split.
// 128x128 tile, BK=64, 3-stage cp.async, 256 threads (warps 2m x 4n).
// ---------------------------------------------------------------------------
static constexpr int GSTAGE = 32768;           // A 16K + B 16K
static constexpr int G_SMEM = 3 * GSTAGE;      // 98304

__device__ __forceinline__ void g_load(
    const __nv_bfloat16* __restrict__ A, const __nv_bfloat16* __restrict__ B,
    int m0, int n0, int kk, int K, uint32_t sA, uint32_t sB, int t)
{
#pragma unroll
    for (int i = 0; i < 4; i++) {
        int idx = t + i * 256;
        int r = idx >> 3, c = idx & 7;
        CP16(sA + SWZ(r, c), (const void*)(A + (size_t)(m0 + r) * K + kk + c * 8));
    }
#pragma unroll
    for (int i = 0; i < 4; i++) {
        int idx = t + i * 256;
        int r = idx >> 3, c = idx & 7;
        CP16(sB + SWZ(r, c), (const void*)(B + (size_t)(n0 + r) * K + kk + c * 8));
    }
}

template <bool GELU, bool RES, bool SPLIT>
__global__ __launch_bounds__(256, 2) void gemm_mma(
    const __nv_bfloat16* __restrict__ Ahi, const __nv_bfloat16* __restrict__ Alo,
    const __nv_bfloat16* __restrict__ Bhi, const __nv_bfloat16* __restrict__ Blo,
    const float* __restrict__ bias, const float* __restrict__ res,
    float* __restrict__ C, __nv_bfloat16* __restrict__ Chi,
    __nv_bfloat16* __restrict__ Clo, int M, int N, int K)
{
    extern __shared__ char smem[];
    const uint32_t sb = smem_u32(smem);
    const int t = threadIdx.x;
    const int wid = t >> 5, lane = t & 31;
    const int wm = wid & 1, wn = wid >> 1;
    const int m0 = blockIdx.y * 128;
    const int n0 = blockIdx.x * 128;

    const int nk = K >> 6;
    const int CC = 3 * nk;

    float acc[4][4][4] = {};

    // prologue: chunks 0, 1
#pragma unroll
    for (int s = 0; s < 2; s++) {
        int tt = s % 3, k = s / 3;
        const __nv_bfloat16* As = (tt == 1) ? Alo : Ahi;
        const __nv_bfloat16* Bs = (tt == 2) ? Blo : Bhi;
        g_load(As, Bs, m0, n0, k * 64, K, sb + s * GSTAGE, sb + s * GSTAGE + 16384, t);
        CP_COMMIT();
    }

    for (int cc = 0; cc < CC; cc++) {
        const int st = cc % 3;
        CP_WAIT(1);
        __syncthreads();
        const int nx = cc + 2;
        if (nx < CC) {
            int tt = nx % 3, k = nx / 3;
            const __nv_bfloat16* As = (tt == 1) ? Alo : Ahi;
            const __nv_bfloat16* Bs = (tt == 2) ? Blo : Bhi;
            int sg = nx % 3;
            g_load(As, Bs, m0, n0, k * 64, K, sb + sg * GSTAGE, sb + sg * GSTAGE + 16384, t);
        }
        CP_COMMIT();

        const uint32_t sA = sb + st * GSTAGE;
        const uint32_t sB = sA + 16384;
#pragma unroll
        for (int p = 0; p < 4; p++) {
            uint32_t af[4][4];
#pragma unroll
            for (int mi = 0; mi < 4; mi++) {
                int row = wm * 64 + mi * 16 + (lane & 15);
                int c   = p * 2 + (lane >> 4);
                ldsm_x4(af[mi], sA + SWZ(row, c));
            }
            uint32_t bf[4][2];
#pragma unroll
            for (int g = 0; g < 2; g++) {
                uint32_t r4[4];
                int row = wn * 32 + g * 16 + (lane & 7) + ((lane >> 4) & 1) * 8;
                int c   = p * 2 + ((lane >> 3) & 1);
                ldsm_x4(r4, sB + SWZ(row, c));
                bf[g * 2 + 0][0] = r4[0]; bf[g * 2 + 0][1] = r4[1];
                bf[g * 2 + 1][0] = r4[2]; bf[g * 2 + 1][1] = r4[3];
            }
#pragma unroll
            for (int mi = 0; mi < 4; mi++)
#pragma unroll
                for (int nj = 0; nj < 4; nj++)
                    mma16816(acc[mi][nj], af[mi], bf[nj][0], bf[nj][1]);
        }
    }

    // epilogue
#pragma unroll
    for (int mi = 0; mi < 4; mi++) {
#pragma unroll
        for (int nj = 0; nj < 4; nj++) {
            const int r0  = m0 + wm * 64 + mi * 16 + (lane >> 2);
            const int col = n0 + wn * 32 + nj * 8 + 2 * (lane & 3);
            const float b0v = bias[col], b1v = bias[col + 1];
            float v00 = acc[mi][nj][0] + b0v, v01 = acc[mi][nj][1] + b1v;
            float v10 = acc[mi][nj][2] + b0v, v11 = acc[mi][nj][3] + b1v;
            if (GELU) {
                v00 = gelu_exact(v00); v01 = gelu_exact(v01);
                v10 = gelu_exact(v10); v11 = gelu_exact(v11);
            }
            if (SPLIT) {
                __nv_bfloat16 h00 = __float2bfloat16(v00), h01 = __float2bfloat16(v01);
                __nv_bfloat16 h10 = __float2bfloat16(v10), h11 = __float2bfloat16(v11);
                *(__nv_bfloat162*)(Chi + (size_t)r0 * N + col) = __halves2bfloat162(h00, h01);
                *(__nv_bfloat162*)(Clo + (size_t)r0 * N + col) = __halves2bfloat162(
                    __float2bfloat16(v00 - __bfloat162float(h00)),
                    __float2bfloat16(v01 - __bfloat162float(h01)));
                *(__nv_bfloat162*)(Chi + (size_t)(r0 + 8) * N + col) = __halves2bfloat162(h10, h11);
                *(__nv_bfloat162*)(Clo + (size_t)(r0 + 8) * N + col) = __halves2bfloat162(
                    __float2bfloat16(v10 - __bfloat162float(h10)),
                    __float2bfloat16(v11 - __bfloat162float(h11)));
            } else {
                if (RES) {
                    v00 += res[(size_t)r0 * N + col];
                    v01 += res[(size_t)r0 * N + col + 1];
                    v10 += res[(size_t)(r0 + 8) * N + col];
                    v11 += res[(size_t)(r0 + 8) * N + col + 1];
                }
                *(float2*)(C + (size_t)r0 * N + col)       = make_float2(v00, v01);
                *(float2*)(C + (size_t)(r0 + 8) * N + col) = make_float2(v10, v11);
            }
        }
    }
}

// ---------------------------------------------------------------------------
// Flash attention via HMMA. 64-query tile, 4 warps (each owns 16 rows).
// S = QK^T with 3-term split (Q,K hi/lo); P·V in bf16 (V hi only).
// SMEM: Qh 8K | Ql 8K | stage{0,1}: Kh 8K, Kl 8K, V 8K  => 64KB
// ---------------------------------------------------------------------------
static constexpr int FA_SMEM = 65536;

__global__ __launch_bounds__(128) void flash_mma(
    const __nv_bfloat16* __restrict__ qh, const __nv_bfloat16* __restrict__ ql,
    const __nv_bfloat16* __restrict__ kh, const __nv_bfloat16* __restrict__ kl,
    const __nv_bfloat16* __restrict__ vh,
    __nv_bfloat16* __restrict__ ch, __nv_bfloat16* __restrict__ cl)
{
    extern __shared__ char smem[];
    const uint32_t sb = smem_u32(smem);
    const int t = threadIdx.x, w = t >> 5, lane = t & 31;
    const int qt = blockIdx.x;
    const int bh = blockIdx.y, bb = bh >> 4, hh = bh & 15;
    const int q0 = qt * 64;
    const size_t rowbase = (size_t)bb * Sc;
    const int colE = hh * 64;

    // Q tile (hi, lo): plain LDG->STS
    for (int i = t; i < 1024; i += 128) {
        int which = i >> 9;
        int r = (i >> 3) & 63, c = i & 7;
        const __nv_bfloat16* src = which ? ql : qh;
        float4 val = *(const float4*)(src + (rowbase + q0 + r) * Ec + colE + c * 8);
        *(float4*)(smem + which * 8192 + SWZ(r, c)) = val;
    }

    // K/V stage loader via cp.async
    auto loadKV = [&](int kt, int stg) {
        uint32_t base = sb + 16384 + stg * 24576;
        for (int i = t; i < 1536; i += 128) {
            int which = i / 512, j = i % 512;
            int r = j >> 3, c = j & 7;
            const __nv_bfloat16* src = (which == 0) ? kh : ((which == 1) ? kl : vh);
            CP16(base + which * 8192 + SWZ(r, c),
                 (const void*)(src + (rowbase + kt * 64 + r) * Ec + colE + c * 8));
        }
    };
    loadKV(0, 0); CP_COMMIT();

    float m_i[2] = {-INFINITY, -INFINITY}, l_i[2] = {0.f, 0.f};
    float o[8][4] = {};
    const int rl = lane >> 2;

    for (int kt = 0; kt <= qt; kt++) {
        if (kt < qt) { loadKV(kt + 1, (kt + 1) & 1); CP_COMMIT(); CP_WAIT(1); }
        else        { CP_WAIT(0); }
        __syncthreads();
        const uint32_t stK = sb + 16384 + (kt & 1) * 24576;
        const uint32_t stV = stK + 16384;

        float sc[8][4] = {};
#pragma unroll
        for (int term = 0; term < 3; term++) {
            const uint32_t aB = sb + ((term == 1) ? 8192 : 0);
            const uint32_t bB = (term == 2) ? (stK + 8192) : stK;
#pragma unroll
            for (int p = 0; p < 4; p++) {
                uint32_t af[4];
                int arow = w * 16 + (lane & 15);
                int ac = p * 2 + (lane >> 4);
                ldsm_x4(af, aB + SWZ(arow, ac));
#pragma unroll
                for (int g = 0; g < 4; g++) {
                    uint32_t r4[4];
                    int brow = g * 16 + (lane & 7) + ((lane >> 4) & 1) * 8;
                    int bc = p * 2 + ((lane >> 3) & 1);
                    ldsm_x4(r4, bB + SWZ(brow, bc));
                    mma16816(sc[g * 2],     af, r4[0], r4[1]);
                    mma16816(sc[g * 2 + 1], af, r4[2], r4[3]);
                }
            }
        }
        // scale + causal mask
#pragma unroll
        for (int nj = 0; nj < 8; nj++)
#pragma unroll
            for (int e = 0; e < 4; e++) {
                sc[nj][e] *= 0.125f;
                if (kt == qt) {
                    int col = nj * 8 + 2 * (lane & 3) + (e & 1);
                    int row = w * 16 + rl + ((e >= 2) ? 8 : 0);
                    if (col > row) sc[nj][e] = -INFINITY;
                }
            }
        // online softmax (2 rows per lane)
        float mx0 = -INFINITY, mx1 = -INFINITY;
#pragma unroll
        for (int nj = 0; nj < 8; nj++) {
            mx0 = fmaxf(mx0, fmaxf(sc[nj][0], sc[nj][1]));
            mx1 = fmaxf(mx1, fmaxf(sc[nj][2], sc[nj][3]));
        }
        mx0 = fmaxf(mx0, __shfl_xor_sync(0xffffffffu, mx0, 1));
        mx0 = fmaxf(mx0, __shfl_xor_sync(0xffffffffu, mx0, 2));
        mx1 = fmaxf(mx1, __shfl_xor_sync(0xffffffffu, mx1, 1));
        mx1 = fmaxf(mx1, __shfl_xor_sync(0xffffffffu, mx1, 2));
        const float mn0 = fmaxf(m_i[0], mx0), mn1 = fmaxf(m_i[1], mx1);
        const float al0 = __expf(m_i[0] - mn0), al1 = __expf(m_i[1] - mn1);
        m_i[0] = mn0; m_i[1] = mn1;
        float rs0 = 0.f, rs1 = 0.f;
#pragma unroll
        for (int nj = 0; nj < 8; nj++) {
            sc[nj][0] = __expf(sc[nj][0] - mn0); rs0 += sc[nj][0];
            sc[nj][1] = __expf(sc[nj][1] - mn0); rs0 += sc[nj][1];
            sc[nj][2] = __expf(sc[nj][2] - mn1); rs1 += sc[nj][2];
            sc[nj][3] = __expf(sc[nj][3] - mn1); rs1 += sc[nj][3];
        }
        rs0 += __shfl_xor_sync(0xffffffffu, rs0, 1);
        rs0 += __shfl_xor_sync(0xffffffffu, rs0, 2);
        rs1 += __shfl_xor_sync(0xffffffffu, rs1, 1);
        rs1 += __shfl_xor_sync(0xffffffffu, rs1, 2);
        l_i[0] = l_i[0] * al0 + rs0;
        l_i[1] = l_i[1] * al1 + rs1;
#pragma unroll
        for (int dj = 0; dj < 8; dj++) {
            o[dj][0] *= al0; o[dj][1] *= al0;
            o[dj][2] *= al1; o[dj][3] *= al1;
        }
        // pack P into A-fragments (k = S columns)
        uint32_t pa[4][4];
#pragma unroll
        for (int s = 0; s < 4; s++) {
            pa[s][0] = pack_bf162(sc[2 * s][0], sc[2 * s][1]);
            pa[s][1] = pack_bf162(sc[2 * s][2], sc[2 * s][3]);
            pa[s][2] = pack_bf162(sc[2 * s + 1][0], sc[2 * s + 1][1]);
            pa[s][3] = pack_bf162(sc[2 * s + 1][2], sc[2 * s + 1][3]);
        }
        // O += P V
#pragma unroll
        for (int s = 0; s < 4; s++) {
#pragma unroll
            for (int g = 0; g < 4; g++) {
                uint32_t r4[4];
                int vrow = s * 16 + (lane & 7) + ((lane >> 3) & 1) * 8;
                int vc = g * 2 + (lane >> 4);
                ldsm_x4_t(r4, stV + SWZ(vrow, vc));
                mma16816(o[g * 2],     pa[s], r4[0], r4[1]);
                mma16816(o[g * 2 + 1], pa[s], r4[2], r4[3]);
            }
        }
        __syncthreads();
    }

    const float inv0 = 1.f / l_i[0], inv1 = 1.f / l_i[1];
#pragma unroll
    for (int dj = 0; dj < 8; dj++) {
        const int d = dj * 8 + 2 * (lane & 3);
        const size_t i0 = (rowbase + q0 + w * 16 + rl) * Ec + colE + d;
        const size_t i1 = i0 + 8 * Ec;
        float v00 = o[dj][0] * inv0, v01 = o[dj][1] * inv0;
        float v10 = o[dj][2] * inv1, v11 = o[dj][3] * inv1;
        __nv_bfloat16 h00 = __float2bfloat16(v00), h01 = __float2bfloat16(v01);
        __nv_bfloat16 h10 = __float2bfloat16(v10), h11 = __float2bfloat16(v11);
        *(__nv_bfloat162*)(ch + i0) = __halves2bfloat162(h00, h01);
        *(__nv_bfloat162*)(cl + i0) = __halves2bfloat162(
            __float2bfloat16(v00 - __bfloat162float(h00)),
            __float2bfloat16(v01 - __bfloat162float(h01)));
        *(__nv_bfloat162*)(ch + i1) = __halves2bfloat162(h10, h11);
        *(__nv_bfloat162*)(cl + i1) = __halves2bfloat162(
            __float2bfloat16(v10 - __bfloat162float(h10)),
            __float2bfloat16(v11 - __bfloat162float(h11)));
    }
}

// ---------------------------------------------------------------------------
// Launch
// ---------------------------------------------------------------------------
extern "C" void kernel_launch(void* const* d_in, const int* in_sizes, int n_in,
                              void* d_out, int out_size)
{
    (void)in_sizes; (void)n_in; (void)out_size;
    const float* x     = (const float*)d_in[0];
    const float* ln1_g = (const float*)d_in[2];
    const float* ln1_b = (const float*)d_in[3];
    const float* Wq = (const float*)d_in[4];
    const float* bq = (const float*)d_in[5];
    const float* Wk = (const float*)d_in[6];
    const float* bk = (const float*)d_in[7];
    const float* Wv = (const float*)d_in[8];
    const float* bv = (const float*)d_in[9];
    const float* Wo = (const float*)d_in[10];
    const float* bo = (const float*)d_in[11];
    const float* ln2_g = (const float*)d_in[12];
    const float* ln2_b = (const float*)d_in[13];
    const float* W1 = (const float*)d_in[14];
    const float* b1 = (const float*)d_in[15];
    const float* W2 = (const float*)d_in[16];
    const float* b2 = (const float*)d_in[17];
    float* out = (float*)d_out;

    __nv_bfloat16 *lnh, *lnl, *qh, *ql, *kh, *kl, *vh, *vl, *ch, *cl, *hh, *hl, *wh, *wl;
    float* x2;
    cudaGetSymbolAddress((void**)&lnh, g_lnh);
    cudaGetSymbolAddress((void**)&lnl, g_lnl);
    cudaGetSymbolAddress((void**)&qh,  g_qh);
    cudaGetSymbolAddress((void**)&ql,  g_ql);
    cudaGetSymbolAddress((void**)&kh,  g_kh);
    cudaGetSymbolAddress((void**)&kl,  g_kl);
    cudaGetSymbolAddress((void**)&vh,  g_vh);
    cudaGetSymbolAddress((void**)&vl,  g_vl);
    cudaGetSymbolAddress((void**)&ch,  g_ch);
    cudaGetSymbolAddress((void**)&cl,  g_cl);
    cudaGetSymbolAddress((void**)&hh,  g_hh);
    cudaGetSymbolAddress((void**)&hl,  g_hl);
    cudaGetSymbolAddress((void**)&wh,  g_wh);
    cudaGetSymbolAddress((void**)&wl,  g_wl);
    cudaGetSymbolAddress((void**)&x2,  g_x2);

    cudaFuncSetAttribute(gemm_mma<false, false, true >, cudaFuncAttributeMaxDynamicSharedMemorySize, G_SMEM);
    cudaFuncSetAttribute(gemm_mma<false, true,  false>, cudaFuncAttributeMaxDynamicSharedMemorySize, G_SMEM);
    cudaFuncSetAttribute(gemm_mma<true,  false, true >, cudaFuncAttributeMaxDynamicSharedMemorySize, G_SMEM);
    cudaFuncSetAttribute(flash_mma, cudaFuncAttributeMaxDynamicSharedMemorySize, FA_SMEM);

    const int nEE4 = Ec * Ec / 4;
    const int nFE4 = Fc * Ec / 4;

    // LN1 -> split
    ln_split_kernel<<<Mc, 256>>>(x, ln1_g, ln1_b, lnh, lnl);
    // Q
    split_kernel<<<(nEE4 + 255) / 256, 256>>>(Wq, wh, wl, nEE4);
    gemm_mma<false, false, true><<<dim3(Ec / 128, Mc / 128), 256, G_SMEM>>>(
        lnh, lnl, wh, wl, bq, nullptr, nullptr, qh, ql, Mc, Ec, Ec);
    // K
    split_kernel<<<(nEE4 + 255) / 256, 256>>>(Wk, wh, wl, nEE4);
    gemm_mma<false, false, true><<<dim3(Ec / 128, Mc / 128), 256, G_SMEM>>>(
        lnh, lnl, wh, wl, bk, nullptr, nullptr, kh, kl, Mc, Ec, Ec);
    // V
    split_kernel<<<(nEE4 + 255) / 256, 256>>>(Wv, wh, wl, nEE4);
    gemm_mma<false, false, true><<<dim3(Ec / 128, Mc / 128), 256, G_SMEM>>>(
        lnh, lnl, wh, wl, bv, nullptr, nullptr, vh, vl, Mc, Ec, Ec);
    // attention
    flash_mma<<<dim3(Sc / 64, Bc * Hc), 128, FA_SMEM>>>(qh, ql, kh, kl, vh, ch, cl);
    // O proj + residual(x) -> x2 (fp32)
    split_kernel<<<(nEE4 + 255) / 256, 256>>>(Wo, wh, wl, nEE4);
    gemm_mma<false, true, false><<<dim3(Ec / 128, Mc / 128), 256, G_SMEM>>>(
        ch, cl, wh, wl, bo, x, x2, nullptr, nullptr, Mc, Ec, Ec);
    // LN2 -> split
    ln_split_kernel<<<Mc, 256>>>(x2, ln2_g, ln2_b, lnh, lnl);
    // FFN up + GELU -> split hid
    split_kernel<<<(nFE4 + 255) / 256, 256>>>(W1, wh, wl, nFE4);
    gemm_mma<true, false, true><<<dim3(Fc / 128, Mc / 128), 256, G_SMEM>>>(
        lnh, lnl, wh, wl, b1, nullptr, nullptr, hh, hl, Mc, Fc, Ec);
    // FFN down + residual(x2) -> out
    split_kernel<<<(nFE4 + 255) / 256, 256>>>(W2, wh, wl, nFE4);
    gemm_mma<false, true, false><<<dim3(Ec / 128, Mc / 128), 256, G_SMEM>>>(
        hh, hl, wh, wl, b2, x2, out, nullptr, nullptr, Mc, Ec, Fc);
}